// round 1
// baseline (speedup 1.0000x reference)
#include <cuda_runtime.h>
#include <math_constants.h>

#define BB 8
#define NN 50000
#define LL 512
#define RR 5

// scratch for per-instance scores (1.6 MB) — __device__ global, no allocation
__device__ float g_scores[BB * NN];

// ---------------------------------------------------------------------------
// Kernel 1: scores[b,n] = dot(x[b,n,:], conv_w) + conv_b   (HBM-bound)
// One warp per instance. Each lane: 4 float4 loads (coalesced 128B per warp
// per load). conv_w staged in shared once per block.
// ---------------------------------------------------------------------------
__global__ __launch_bounds__(256) void chowder_scores_kernel(
    const float* __restrict__ x,
    const float* __restrict__ conv_w,
    const float* __restrict__ conv_b)
{
    __shared__ float4 ws[LL / 4];
    const int tid = threadIdx.x;

    // stage conv_w (2 KB) into shared
    for (int i = tid; i < LL / 4; i += blockDim.x)
        ws[i] = reinterpret_cast<const float4*>(conv_w)[i];
    __syncthreads();

    const int warp = tid >> 5;
    const int lane = tid & 31;
    const long long inst = (long long)blockIdx.x * (blockDim.x >> 5) + warp;
    if (inst >= (long long)BB * NN) return;

    const float4* __restrict__ xp =
        reinterpret_cast<const float4*>(x + inst * LL);

    float acc = 0.0f;
#pragma unroll
    for (int it = 0; it < 4; it++) {
        float4 v = xp[it * 32 + lane];
        float4 w = ws[it * 32 + lane];
        acc = fmaf(v.x, w.x, acc);
        acc = fmaf(v.y, w.y, acc);
        acc = fmaf(v.z, w.z, acc);
        acc = fmaf(v.w, w.w, acc);
    }
#pragma unroll
    for (int o = 16; o; o >>= 1)
        acc += __shfl_xor_sync(0xffffffff, acc, o);

    if (lane == 0)
        g_scores[inst] = acc + conv_b[0];
}

// ---------------------------------------------------------------------------
// Kernel 2: per-batch top-5 (descending) + bottom-5 (ascending) + MLP.
// One block per batch, 256 threads. Two-stage shared-memory merge.
// ---------------------------------------------------------------------------
__device__ __forceinline__ void insert_max(float* arr, float v) {
    // arr sorted descending; keep 5 largest
    if (v > arr[RR - 1]) {
        arr[RR - 1] = v;
#pragma unroll
        for (int j = RR - 1; j > 0; j--) {
            if (arr[j] > arr[j - 1]) {
                float t = arr[j]; arr[j] = arr[j - 1]; arr[j - 1] = t;
            }
        }
    }
}
__device__ __forceinline__ void insert_min(float* arr, float v) {
    // arr sorted ascending; keep 5 smallest
    if (v < arr[RR - 1]) {
        arr[RR - 1] = v;
#pragma unroll
        for (int j = RR - 1; j > 0; j--) {
            if (arr[j] < arr[j - 1]) {
                float t = arr[j]; arr[j] = arr[j - 1]; arr[j - 1] = t;
            }
        }
    }
}

__global__ __launch_bounds__(256) void chowder_topk_mlp_kernel(
    const float* __restrict__ w1, const float* __restrict__ b1,
    const float* __restrict__ w2, const float* __restrict__ b2,
    const float* __restrict__ w3, const float* __restrict__ b3,
    float* __restrict__ out)
{
    const int b   = blockIdx.x;
    const int tid = threadIdx.x;
    const float* __restrict__ s = g_scores + (long long)b * NN;

    float top[RR], bot[RR];
#pragma unroll
    for (int i = 0; i < RR; i++) { top[i] = -CUDART_INF_F; bot[i] = CUDART_INF_F; }

    for (int i = tid; i < NN; i += blockDim.x) {
        float v = s[i];
        insert_max(top, v);
        insert_min(bot, v);
    }

    __shared__ float stop[256 * RR];
    __shared__ float sbot[256 * RR];
    __shared__ float cat[2 * RR];
    __shared__ float h1[200];
    __shared__ float h2[100];

#pragma unroll
    for (int j = 0; j < RR; j++) { stop[tid * RR + j] = top[j]; sbot[tid * RR + j] = bot[j]; }
    __syncthreads();

    // stage 2: warp 0 merges 1280 candidates down to 160
    if (tid < 32) {
        float t2[RR], b2l[RR];
#pragma unroll
        for (int i = 0; i < RR; i++) { t2[i] = -CUDART_INF_F; b2l[i] = CUDART_INF_F; }
        for (int i = tid; i < 256 * RR; i += 32) {
            insert_max(t2, stop[i]);
            insert_min(b2l, sbot[i]);
        }
#pragma unroll
        for (int j = 0; j < RR; j++) { stop[tid * RR + j] = t2[j]; sbot[tid * RR + j] = b2l[j]; }
        __syncwarp();

        // stage 3: lane 0 merges 160 candidates to final 5
        if (tid == 0) {
            float ft[RR], fb[RR];
#pragma unroll
            for (int i = 0; i < RR; i++) { ft[i] = -CUDART_INF_F; fb[i] = CUDART_INF_F; }
            for (int i = 0; i < 32 * RR; i++) {
                insert_max(ft, stop[i]);
                insert_min(fb, sbot[i]);
            }
            // cat = [min_vals ascending, max_vals descending]
#pragma unroll
            for (int j = 0; j < RR; j++) { cat[j] = fb[j]; cat[RR + j] = ft[j]; }
        }
    }
    __syncthreads();

    // --- tiny MLP (no activations) ---
    // h1[200] = cat[10] @ w1[10,200] + b1
    if (tid < 200) {
        float a = b1[tid];
#pragma unroll
        for (int i = 0; i < 2 * RR; i++)
            a = fmaf(cat[i], w1[i * 200 + tid], a);
        h1[tid] = a;
    }
    __syncthreads();
    // h2[100] = h1[200] @ w2[200,100] + b2
    if (tid < 100) {
        float a = b2[tid];
        for (int k = 0; k < 200; k++)
            a = fmaf(h1[k], w2[k * 100 + tid], a);
        h2[tid] = a;
    }
    __syncthreads();
    // out[2] = h2[100] @ w3[100,2] + b3
    if (tid < 2) {
        float a = b3[tid];
        for (int k = 0; k < 100; k++)
            a = fmaf(h2[k], w3[k * 2 + tid], a);
        out[b * 2 + tid] = a;
    }
}

// ---------------------------------------------------------------------------
extern "C" void kernel_launch(void* const* d_in, const int* in_sizes, int n_in,
                              void* d_out, int out_size)
{
    const float* x      = (const float*)d_in[0];
    const float* conv_w = (const float*)d_in[1];
    const float* conv_b = (const float*)d_in[2];
    const float* w1     = (const float*)d_in[3];
    const float* b1     = (const float*)d_in[4];
    const float* w2     = (const float*)d_in[5];
    const float* b2     = (const float*)d_in[6];
    const float* w3     = (const float*)d_in[7];
    const float* b3     = (const float*)d_in[8];
    float* out          = (float*)d_out;

    // 400000 instances, 1 warp each, 8 warps/block -> 50000 blocks
    const int threads = 256;
    const int warps_per_block = threads / 32;
    const int blocks = (BB * NN + warps_per_block - 1) / warps_per_block;

    chowder_scores_kernel<<<blocks, threads>>>(x, conv_w, conv_b);
    chowder_topk_mlp_kernel<<<BB, 256>>>(w1, b1, w2, b2, w3, b3, out);
}

// round 2
// speedup vs baseline: 1.1554x; 1.1554x over previous
#include <cuda_runtime.h>
#include <math_constants.h>

#define BB 8
#define NN 50000
#define LL 512
#define RR 5
#define NPART 96           // partial-topk blocks per batch
#define CHUNK ((NN + NPART - 1) / NPART)   // 521

// scratch: per-instance scores (1.6 MB) + per-block partial top/bot candidates
__device__ float g_scores[BB * NN];
__device__ float g_part_top[BB * NPART * RR];
__device__ float g_part_bot[BB * NPART * RR];

// ---------------------------------------------------------------------------
// Kernel 1: scores[b,n] = dot(x[b,n,:], conv_w) + conv_b   (HBM-bound)
// One warp per instance; 4x float4 per lane; conv_w staged in shared.
// Measured at 7.5 TB/s — at roofline, do not touch.
// ---------------------------------------------------------------------------
__global__ __launch_bounds__(256) void chowder_scores_kernel(
    const float* __restrict__ x,
    const float* __restrict__ conv_w,
    const float* __restrict__ conv_b)
{
    __shared__ float4 ws[LL / 4];
    const int tid = threadIdx.x;

    for (int i = tid; i < LL / 4; i += blockDim.x)
        ws[i] = reinterpret_cast<const float4*>(conv_w)[i];
    __syncthreads();

    const int warp = tid >> 5;
    const int lane = tid & 31;
    const long long inst = (long long)blockIdx.x * (blockDim.x >> 5) + warp;
    if (inst >= (long long)BB * NN) return;

    const float4* __restrict__ xp =
        reinterpret_cast<const float4*>(x + inst * LL);

    float acc = 0.0f;
#pragma unroll
    for (int it = 0; it < 4; it++) {
        float4 v = xp[it * 32 + lane];
        float4 w = ws[it * 32 + lane];
        acc = fmaf(v.x, w.x, acc);
        acc = fmaf(v.y, w.y, acc);
        acc = fmaf(v.z, w.z, acc);
        acc = fmaf(v.w, w.w, acc);
    }
#pragma unroll
    for (int o = 16; o; o >>= 1)
        acc += __shfl_xor_sync(0xffffffff, acc, o);

    if (lane == 0)
        g_scores[inst] = acc + conv_b[0];
}

// ---------------------------------------------------------------------------
// small sorted-insertion helpers (registers, fully unrolled)
// ---------------------------------------------------------------------------
__device__ __forceinline__ void insert_max(float* arr, float v) {
    if (v > arr[RR - 1]) {
        arr[RR - 1] = v;
#pragma unroll
        for (int j = RR - 1; j > 0; j--) {
            if (arr[j] > arr[j - 1]) {
                float t = arr[j]; arr[j] = arr[j - 1]; arr[j - 1] = t;
            }
        }
    }
}
__device__ __forceinline__ void insert_min(float* arr, float v) {
    if (v < arr[RR - 1]) {
        arr[RR - 1] = v;
#pragma unroll
        for (int j = RR - 1; j > 0; j--) {
            if (arr[j] < arr[j - 1]) {
                float t = arr[j]; arr[j] = arr[j - 1]; arr[j - 1] = t;
            }
        }
    }
}

// ---------------------------------------------------------------------------
// Kernel 2a: partial top-5/bot-5. grid = (NPART, BB), 256 threads.
// Each block covers CHUNK scores (~2 per thread), merges 256->32->1,
// writes 5+5 candidates to g_part_*.
// ---------------------------------------------------------------------------
__global__ __launch_bounds__(256) void chowder_partial_topk_kernel()
{
    const int p   = blockIdx.x;
    const int b   = blockIdx.y;
    const int tid = threadIdx.x;

    const int start = p * CHUNK;
    const int end   = min(start + CHUNK, NN);
    const float* __restrict__ s = g_scores + (long long)b * NN;

    float top[RR], bot[RR];
#pragma unroll
    for (int i = 0; i < RR; i++) { top[i] = -CUDART_INF_F; bot[i] = CUDART_INF_F; }

    for (int i = start + tid; i < end; i += blockDim.x) {
        float v = s[i];
        insert_max(top, v);
        insert_min(bot, v);
    }

    __shared__ float stop[256 * RR];
    __shared__ float sbot[256 * RR];
#pragma unroll
    for (int j = 0; j < RR; j++) { stop[tid * RR + j] = top[j]; sbot[tid * RR + j] = bot[j]; }
    __syncthreads();

    if (tid < 32) {
        float t2[RR], b2[RR];
#pragma unroll
        for (int i = 0; i < RR; i++) { t2[i] = -CUDART_INF_F; b2[i] = CUDART_INF_F; }
        for (int i = tid; i < 256 * RR; i += 32) {
            insert_max(t2, stop[i]);
            insert_min(b2, sbot[i]);
        }
#pragma unroll
        for (int j = 0; j < RR; j++) { stop[tid * RR + j] = t2[j]; sbot[tid * RR + j] = b2[j]; }
        __syncwarp();

        if (tid == 0) {
            float ft[RR], fb[RR];
#pragma unroll
            for (int i = 0; i < RR; i++) { ft[i] = -CUDART_INF_F; fb[i] = CUDART_INF_F; }
            for (int i = 0; i < 32 * RR; i++) {
                insert_max(ft, stop[i]);
                insert_min(fb, sbot[i]);
            }
            float* pt = g_part_top + ((long long)b * NPART + p) * RR;
            float* pb = g_part_bot + ((long long)b * NPART + p) * RR;
#pragma unroll
            for (int j = 0; j < RR; j++) { pt[j] = ft[j]; pb[j] = fb[j]; }
        }
    }
}

// ---------------------------------------------------------------------------
// Kernel 2b: merge NPART partials per batch + MLP. grid = BB, 256 threads.
// ---------------------------------------------------------------------------
__global__ __launch_bounds__(256) void chowder_merge_mlp_kernel(
    const float* __restrict__ w1, const float* __restrict__ b1,
    const float* __restrict__ w2, const float* __restrict__ b2,
    const float* __restrict__ w3, const float* __restrict__ b3,
    float* __restrict__ out)
{
    const int b   = blockIdx.x;
    const int tid = threadIdx.x;

    __shared__ float stop[32 * RR];
    __shared__ float sbot[32 * RR];
    __shared__ float cat[2 * RR];
    __shared__ float h1[200];
    __shared__ float h2[100];

    if (tid < 32) {
        const float* pt = g_part_top + (long long)b * NPART * RR;
        const float* pb = g_part_bot + (long long)b * NPART * RR;
        float t2[RR], b2l[RR];
#pragma unroll
        for (int i = 0; i < RR; i++) { t2[i] = -CUDART_INF_F; b2l[i] = CUDART_INF_F; }
        for (int i = tid; i < NPART * RR; i += 32) {
            insert_max(t2, pt[i]);
            insert_min(b2l, pb[i]);
        }
#pragma unroll
        for (int j = 0; j < RR; j++) { stop[tid * RR + j] = t2[j]; sbot[tid * RR + j] = b2l[j]; }
        __syncwarp();

        if (tid == 0) {
            float ft[RR], fb[RR];
#pragma unroll
            for (int i = 0; i < RR; i++) { ft[i] = -CUDART_INF_F; fb[i] = CUDART_INF_F; }
            for (int i = 0; i < 32 * RR; i++) {
                insert_max(ft, stop[i]);
                insert_min(fb, sbot[i]);
            }
            // cat = [min_vals ascending, max_vals descending]
#pragma unroll
            for (int j = 0; j < RR; j++) { cat[j] = fb[j]; cat[RR + j] = ft[j]; }
        }
    }
    __syncthreads();

    // --- tiny MLP (no activations) ---
    if (tid < 200) {
        float a = b1[tid];
#pragma unroll
        for (int i = 0; i < 2 * RR; i++)
            a = fmaf(cat[i], w1[i * 200 + tid], a);
        h1[tid] = a;
    }
    __syncthreads();
    if (tid < 100) {
        float a = b2[tid];
        for (int k = 0; k < 200; k++)
            a = fmaf(h1[k], w2[k * 100 + tid], a);
        h2[tid] = a;
    }
    __syncthreads();
    if (tid < 2) {
        float a = b3[tid];
        for (int k = 0; k < 100; k++)
            a = fmaf(h2[k], w3[k * 2 + tid], a);
        out[b * 2 + tid] = a;
    }
}

// ---------------------------------------------------------------------------
extern "C" void kernel_launch(void* const* d_in, const int* in_sizes, int n_in,
                              void* d_out, int out_size)
{
    const float* x      = (const float*)d_in[0];
    const float* conv_w = (const float*)d_in[1];
    const float* conv_b = (const float*)d_in[2];
    const float* w1     = (const float*)d_in[3];
    const float* b1     = (const float*)d_in[4];
    const float* w2     = (const float*)d_in[5];
    const float* b2     = (const float*)d_in[6];
    const float* w3     = (const float*)d_in[7];
    const float* b3     = (const float*)d_in[8];
    float* out          = (float*)d_out;

    const int threads = 256;
    const int warps_per_block = threads / 32;
    const int blocks = (BB * NN + warps_per_block - 1) / warps_per_block;

    chowder_scores_kernel<<<blocks, threads>>>(x, conv_w, conv_b);

    dim3 pgrid(NPART, BB);
    chowder_partial_topk_kernel<<<pgrid, 256>>>();

    chowder_merge_mlp_kernel<<<BB, 256>>>(w1, b1, w2, b2, w3, b3, out);
}

// round 3
// speedup vs baseline: 1.1561x; 1.0006x over previous
#include <cuda_runtime.h>
#include <math_constants.h>

#define BB 8
#define NN 50000
#define LL 512
#define RR 5
#define NPART 96           // partial-topk blocks per batch
#define CHUNK ((NN + NPART - 1) / NPART)   // 521

// scratch: per-instance scores (1.6 MB) + per-block partial top/bot candidates
__device__ float g_scores[BB * NN];
__device__ float g_part_top[BB * NPART * RR];
__device__ float g_part_bot[BB * NPART * RR];

// ---------------------------------------------------------------------------
// Kernel 1: scores[b,n] = dot(x[b,n,:], conv_w) + conv_b   (HBM-bound)
// One warp per instance; 4x float4 per lane; conv_w staged in shared.
// Measured at 7.5 TB/s — at roofline, do not touch.
// ---------------------------------------------------------------------------
__global__ __launch_bounds__(256) void chowder_scores_kernel(
    const float* __restrict__ x,
    const float* __restrict__ conv_w,
    const float* __restrict__ conv_b)
{
    __shared__ float4 ws[LL / 4];
    const int tid = threadIdx.x;

    for (int i = tid; i < LL / 4; i += blockDim.x)
        ws[i] = reinterpret_cast<const float4*>(conv_w)[i];
    __syncthreads();

    const int warp = tid >> 5;
    const int lane = tid & 31;
    const long long inst = (long long)blockIdx.x * (blockDim.x >> 5) + warp;
    if (inst >= (long long)BB * NN) return;

    const float4* __restrict__ xp =
        reinterpret_cast<const float4*>(x + inst * LL);

    float acc = 0.0f;
#pragma unroll
    for (int it = 0; it < 4; it++) {
        float4 v = xp[it * 32 + lane];
        float4 w = ws[it * 32 + lane];
        acc = fmaf(v.x, w.x, acc);
        acc = fmaf(v.y, w.y, acc);
        acc = fmaf(v.z, w.z, acc);
        acc = fmaf(v.w, w.w, acc);
    }
#pragma unroll
    for (int o = 16; o; o >>= 1)
        acc += __shfl_xor_sync(0xffffffff, acc, o);

    if (lane == 0)
        g_scores[inst] = acc + conv_b[0];
}

// ---------------------------------------------------------------------------
// small sorted-insertion helpers (registers, fully unrolled)
// ---------------------------------------------------------------------------
__device__ __forceinline__ void insert_max(float* arr, float v) {
    if (v > arr[RR - 1]) {
        arr[RR - 1] = v;
#pragma unroll
        for (int j = RR - 1; j > 0; j--) {
            if (arr[j] > arr[j - 1]) {
                float t = arr[j]; arr[j] = arr[j - 1]; arr[j - 1] = t;
            }
        }
    }
}
__device__ __forceinline__ void insert_min(float* arr, float v) {
    if (v < arr[RR - 1]) {
        arr[RR - 1] = v;
#pragma unroll
        for (int j = RR - 1; j > 0; j--) {
            if (arr[j] < arr[j - 1]) {
                float t = arr[j]; arr[j] = arr[j - 1]; arr[j - 1] = t;
            }
        }
    }
}

// ---------------------------------------------------------------------------
// Kernel 2a: partial top-5/bot-5. grid = (NPART, BB), 256 threads.
// Each block covers CHUNK scores (~2 per thread), merges 256->32->1,
// writes 5+5 candidates to g_part_*.
// ---------------------------------------------------------------------------
__global__ __launch_bounds__(256) void chowder_partial_topk_kernel()
{
    const int p   = blockIdx.x;
    const int b   = blockIdx.y;
    const int tid = threadIdx.x;

    const int start = p * CHUNK;
    const int end   = min(start + CHUNK, NN);
    const float* __restrict__ s = g_scores + (long long)b * NN;

    float top[RR], bot[RR];
#pragma unroll
    for (int i = 0; i < RR; i++) { top[i] = -CUDART_INF_F; bot[i] = CUDART_INF_F; }

    for (int i = start + tid; i < end; i += blockDim.x) {
        float v = s[i];
        insert_max(top, v);
        insert_min(bot, v);
    }

    __shared__ float stop[256 * RR];
    __shared__ float sbot[256 * RR];
#pragma unroll
    for (int j = 0; j < RR; j++) { stop[tid * RR + j] = top[j]; sbot[tid * RR + j] = bot[j]; }
    __syncthreads();

    if (tid < 32) {
        float t2[RR], b2[RR];
#pragma unroll
        for (int i = 0; i < RR; i++) { t2[i] = -CUDART_INF_F; b2[i] = CUDART_INF_F; }
        for (int i = tid; i < 256 * RR; i += 32) {
            insert_max(t2, stop[i]);
            insert_min(b2, sbot[i]);
        }
#pragma unroll
        for (int j = 0; j < RR; j++) { stop[tid * RR + j] = t2[j]; sbot[tid * RR + j] = b2[j]; }
        __syncwarp();

        if (tid == 0) {
            float ft[RR], fb[RR];
#pragma unroll
            for (int i = 0; i < RR; i++) { ft[i] = -CUDART_INF_F; fb[i] = CUDART_INF_F; }
            for (int i = 0; i < 32 * RR; i++) {
                insert_max(ft, stop[i]);
                insert_min(fb, sbot[i]);
            }
            float* pt = g_part_top + ((long long)b * NPART + p) * RR;
            float* pb = g_part_bot + ((long long)b * NPART + p) * RR;
#pragma unroll
            for (int j = 0; j < RR; j++) { pt[j] = ft[j]; pb[j] = fb[j]; }
        }
    }
}

// ---------------------------------------------------------------------------
// Kernel 2b: merge NPART partials per batch + MLP. grid = BB, 256 threads.
// ---------------------------------------------------------------------------
__global__ __launch_bounds__(256) void chowder_merge_mlp_kernel(
    const float* __restrict__ w1, const float* __restrict__ b1,
    const float* __restrict__ w2, const float* __restrict__ b2,
    const float* __restrict__ w3, const float* __restrict__ b3,
    float* __restrict__ out)
{
    const int b   = blockIdx.x;
    const int tid = threadIdx.x;

    __shared__ float stop[32 * RR];
    __shared__ float sbot[32 * RR];
    __shared__ float cat[2 * RR];
    __shared__ float h1[200];
    __shared__ float h2[100];

    if (tid < 32) {
        const float* pt = g_part_top + (long long)b * NPART * RR;
        const float* pb = g_part_bot + (long long)b * NPART * RR;
        float t2[RR], b2l[RR];
#pragma unroll
        for (int i = 0; i < RR; i++) { t2[i] = -CUDART_INF_F; b2l[i] = CUDART_INF_F; }
        for (int i = tid; i < NPART * RR; i += 32) {
            insert_max(t2, pt[i]);
            insert_min(b2l, pb[i]);
        }
#pragma unroll
        for (int j = 0; j < RR; j++) { stop[tid * RR + j] = t2[j]; sbot[tid * RR + j] = b2l[j]; }
        __syncwarp();

        if (tid == 0) {
            float ft[RR], fb[RR];
#pragma unroll
            for (int i = 0; i < RR; i++) { ft[i] = -CUDART_INF_F; fb[i] = CUDART_INF_F; }
            for (int i = 0; i < 32 * RR; i++) {
                insert_max(ft, stop[i]);
                insert_min(fb, sbot[i]);
            }
            // cat = [min_vals ascending, max_vals descending]
#pragma unroll
            for (int j = 0; j < RR; j++) { cat[j] = fb[j]; cat[RR + j] = ft[j]; }
        }
    }
    __syncthreads();

    // --- tiny MLP (no activations) ---
    if (tid < 200) {
        float a = b1[tid];
#pragma unroll
        for (int i = 0; i < 2 * RR; i++)
            a = fmaf(cat[i], w1[i * 200 + tid], a);
        h1[tid] = a;
    }
    __syncthreads();
    if (tid < 100) {
        float a = b2[tid];
        for (int k = 0; k < 200; k++)
            a = fmaf(h1[k], w2[k * 100 + tid], a);
        h2[tid] = a;
    }
    __syncthreads();
    if (tid < 2) {
        float a = b3[tid];
        for (int k = 0; k < 100; k++)
            a = fmaf(h2[k], w3[k * 2 + tid], a);
        out[b * 2 + tid] = a;
    }
}

// ---------------------------------------------------------------------------
extern "C" void kernel_launch(void* const* d_in, const int* in_sizes, int n_in,
                              void* d_out, int out_size)
{
    const float* x      = (const float*)d_in[0];
    const float* conv_w = (const float*)d_in[1];
    const float* conv_b = (const float*)d_in[2];
    const float* w1     = (const float*)d_in[3];
    const float* b1     = (const float*)d_in[4];
    const float* w2     = (const float*)d_in[5];
    const float* b2     = (const float*)d_in[6];
    const float* w3     = (const float*)d_in[7];
    const float* b3     = (const float*)d_in[8];
    float* out          = (float*)d_out;

    const int threads = 256;
    const int warps_per_block = threads / 32;
    const int blocks = (BB * NN + warps_per_block - 1) / warps_per_block;

    chowder_scores_kernel<<<blocks, threads>>>(x, conv_w, conv_b);

    dim3 pgrid(NPART, BB);
    chowder_partial_topk_kernel<<<pgrid, 256>>>();

    chowder_merge_mlp_kernel<<<BB, 256>>>(w1, b1, w2, b2, w3, b3, out);
}

// round 4
// speedup vs baseline: 1.1824x; 1.0228x over previous
#include <cuda_runtime.h>
#include <math_constants.h>

#define BB 8
#define NN 50000
#define LL 512
#define RR 5
#define GPB 256                 // blocks per batch in the fused kernel
#define WPB 8                   // warps per block
#define WARPS_PER_BATCH (GPB * WPB)   // 2048

// partial top/bot candidates: one 5+5 set per block per batch (80 KB total)
__device__ float g_part_top[BB * GPB * RR];
__device__ float g_part_bot[BB * GPB * RR];

// ---------------------------------------------------------------------------
// sorted-insertion helpers (registers, fully unrolled, rarely-taken branch)
// ---------------------------------------------------------------------------
__device__ __forceinline__ void insert_max(float* arr, float v) {
    if (v > arr[RR - 1]) {
        arr[RR - 1] = v;
#pragma unroll
        for (int j = RR - 1; j > 0; j--) {
            if (arr[j] > arr[j - 1]) {
                float t = arr[j]; arr[j] = arr[j - 1]; arr[j - 1] = t;
            }
        }
    }
}
__device__ __forceinline__ void insert_min(float* arr, float v) {
    if (v < arr[RR - 1]) {
        arr[RR - 1] = v;
#pragma unroll
        for (int j = RR - 1; j > 0; j--) {
            if (arr[j] < arr[j - 1]) {
                float t = arr[j]; arr[j] = arr[j - 1]; arr[j - 1] = t;
            }
        }
    }
}

// ---------------------------------------------------------------------------
// Fused kernel: scores + running top-5/bot-5. grid = (GPB, BB), 256 threads.
// Each warp computes ~25 instance scores (coalesced 4x float4 per lane) and
// lane 0 maintains register top/bot lists. Block merges 8 warps -> 1 partial.
// Scores are never written to memory.
// ---------------------------------------------------------------------------
__global__ __launch_bounds__(256) void chowder_scores_topk_kernel(
    const float* __restrict__ x,
    const float* __restrict__ conv_w,
    const float* __restrict__ conv_b)
{
    __shared__ float4 ws[LL / 4];
    __shared__ float stop[WPB * RR];
    __shared__ float sbot[WPB * RR];

    const int tid  = threadIdx.x;
    const int warp = tid >> 5;
    const int lane = tid & 31;
    const int b    = blockIdx.y;

    for (int i = tid; i < LL / 4; i += blockDim.x)
        ws[i] = reinterpret_cast<const float4*>(conv_w)[i];
    __syncthreads();

    // preload weights into registers (reused every iteration)
    float4 w0 = ws[0 * 32 + lane];
    float4 w1r = ws[1 * 32 + lane];
    float4 w2r = ws[2 * 32 + lane];
    float4 w3r = ws[3 * 32 + lane];

    const int gw = blockIdx.x * WPB + warp;   // warp index within batch
    const float cb = conv_b[0];
    const float* __restrict__ xb = x + (long long)b * NN * LL;

    float top[RR], bot[RR];
#pragma unroll
    for (int i = 0; i < RR; i++) { top[i] = -CUDART_INF_F; bot[i] = CUDART_INF_F; }

    for (int inst = gw; inst < NN; inst += WARPS_PER_BATCH) {
        const float4* __restrict__ xp =
            reinterpret_cast<const float4*>(xb + (long long)inst * LL);

        float4 v0 = xp[0 * 32 + lane];
        float4 v1 = xp[1 * 32 + lane];
        float4 v2 = xp[2 * 32 + lane];
        float4 v3 = xp[3 * 32 + lane];

        float acc = 0.0f;
        acc = fmaf(v0.x, w0.x,  acc); acc = fmaf(v0.y, w0.y,  acc);
        acc = fmaf(v0.z, w0.z,  acc); acc = fmaf(v0.w, w0.w,  acc);
        acc = fmaf(v1.x, w1r.x, acc); acc = fmaf(v1.y, w1r.y, acc);
        acc = fmaf(v1.z, w1r.z, acc); acc = fmaf(v1.w, w1r.w, acc);
        acc = fmaf(v2.x, w2r.x, acc); acc = fmaf(v2.y, w2r.y, acc);
        acc = fmaf(v2.z, w2r.z, acc); acc = fmaf(v2.w, w2r.w, acc);
        acc = fmaf(v3.x, w3r.x, acc); acc = fmaf(v3.y, w3r.y, acc);
        acc = fmaf(v3.z, w3r.z, acc); acc = fmaf(v3.w, w3r.w, acc);

#pragma unroll
        for (int o = 16; o; o >>= 1)
            acc += __shfl_xor_sync(0xffffffff, acc, o);

        if (lane == 0) {
            float v = acc + cb;
            insert_max(top, v);
            insert_min(bot, v);
        }
    }

    // block merge: 8 warps' candidates -> 1 partial set
    if (lane == 0) {
#pragma unroll
        for (int j = 0; j < RR; j++) {
            stop[warp * RR + j] = top[j];
            sbot[warp * RR + j] = bot[j];
        }
    }
    __syncthreads();

    if (tid == 0) {
        float ft[RR], fb[RR];
#pragma unroll
        for (int i = 0; i < RR; i++) { ft[i] = -CUDART_INF_F; fb[i] = CUDART_INF_F; }
        for (int i = 0; i < WPB * RR; i++) {
            insert_max(ft, stop[i]);
            insert_min(fb, sbot[i]);
        }
        float* pt = g_part_top + ((long long)b * GPB + blockIdx.x) * RR;
        float* pb = g_part_bot + ((long long)b * GPB + blockIdx.x) * RR;
#pragma unroll
        for (int j = 0; j < RR; j++) { pt[j] = ft[j]; pb[j] = fb[j]; }
    }
}

// ---------------------------------------------------------------------------
// Merge GPB partials per batch + MLP. grid = BB, 256 threads.
// ---------------------------------------------------------------------------
__global__ __launch_bounds__(256) void chowder_merge_mlp_kernel(
    const float* __restrict__ w1, const float* __restrict__ b1,
    const float* __restrict__ w2, const float* __restrict__ b2,
    const float* __restrict__ w3, const float* __restrict__ b3,
    float* __restrict__ out)
{
    const int b   = blockIdx.x;
    const int tid = threadIdx.x;

    __shared__ float stop[32 * RR];
    __shared__ float sbot[32 * RR];
    __shared__ float cat[2 * RR];
    __shared__ float h1[200];
    __shared__ float h2[100];

    if (tid < 32) {
        const float* pt = g_part_top + (long long)b * GPB * RR;
        const float* pb = g_part_bot + (long long)b * GPB * RR;
        float t2[RR], b2l[RR];
#pragma unroll
        for (int i = 0; i < RR; i++) { t2[i] = -CUDART_INF_F; b2l[i] = CUDART_INF_F; }
        for (int i = tid; i < GPB * RR; i += 32) {
            insert_max(t2, pt[i]);
            insert_min(b2l, pb[i]);
        }
#pragma unroll
        for (int j = 0; j < RR; j++) { stop[tid * RR + j] = t2[j]; sbot[tid * RR + j] = b2l[j]; }
        __syncwarp();

        if (tid == 0) {
            float ft[RR], fb[RR];
#pragma unroll
            for (int i = 0; i < RR; i++) { ft[i] = -CUDART_INF_F; fb[i] = CUDART_INF_F; }
            for (int i = 0; i < 32 * RR; i++) {
                insert_max(ft, stop[i]);
                insert_min(fb, sbot[i]);
            }
            // cat = [min_vals ascending, max_vals descending]
#pragma unroll
            for (int j = 0; j < RR; j++) { cat[j] = fb[j]; cat[RR + j] = ft[j]; }
        }
    }
    __syncthreads();

    // --- tiny MLP (no activations) ---
    if (tid < 200) {
        float a = b1[tid];
#pragma unroll
        for (int i = 0; i < 2 * RR; i++)
            a = fmaf(cat[i], w1[i * 200 + tid], a);
        h1[tid] = a;
    }
    __syncthreads();
    if (tid < 100) {
        float a = b2[tid];
        for (int k = 0; k < 200; k++)
            a = fmaf(h1[k], w2[k * 100 + tid], a);
        h2[tid] = a;
    }
    __syncthreads();
    if (tid < 2) {
        float a = b3[tid];
        for (int k = 0; k < 100; k++)
            a = fmaf(h2[k], w3[k * 2 + tid], a);
        out[b * 2 + tid] = a;
    }
}

// ---------------------------------------------------------------------------
extern "C" void kernel_launch(void* const* d_in, const int* in_sizes, int n_in,
                              void* d_out, int out_size)
{
    const float* x      = (const float*)d_in[0];
    const float* conv_w = (const float*)d_in[1];
    const float* conv_b = (const float*)d_in[2];
    const float* w1     = (const float*)d_in[3];
    const float* b1     = (const float*)d_in[4];
    const float* w2     = (const float*)d_in[5];
    const float* b2     = (const float*)d_in[6];
    const float* w3     = (const float*)d_in[7];
    const float* b3     = (const float*)d_in[8];
    float* out          = (float*)d_out;

    dim3 grid(GPB, BB);
    chowder_scores_topk_kernel<<<grid, 256>>>(x, conv_w, conv_b);
    chowder_merge_mlp_kernel<<<BB, 256>>>(w1, b1, w2, b2, w3, b3, out);
}

// round 5
// speedup vs baseline: 1.2022x; 1.0167x over previous
#include <cuda_runtime.h>
#include <math_constants.h>

#define BB 8
#define NN 50000
#define LL 512
#define RR 5
#define GPB 256                 // blocks per batch in the fused kernel
#define WPB 8                   // warps per block
#define WARPS_PER_BATCH (GPB * WPB)   // 2048

// partial top/bot candidates: one sorted 5+5 set per block per batch
__device__ float g_part_top[BB * GPB * RR];   // sorted descending per 5-group
__device__ float g_part_bot[BB * GPB * RR];   // sorted ascending per 5-group

// ---------------------------------------------------------------------------
// sorted-insertion helpers (registers, fully unrolled, rarely-taken branch)
// ---------------------------------------------------------------------------
__device__ __forceinline__ void insert_max(float* arr, float v) {
    if (v > arr[RR - 1]) {
        arr[RR - 1] = v;
#pragma unroll
        for (int j = RR - 1; j > 0; j--) {
            if (arr[j] > arr[j - 1]) {
                float t = arr[j]; arr[j] = arr[j - 1]; arr[j - 1] = t;
            }
        }
    }
}
__device__ __forceinline__ void insert_min(float* arr, float v) {
    if (v < arr[RR - 1]) {
        arr[RR - 1] = v;
#pragma unroll
        for (int j = RR - 1; j > 0; j--) {
            if (arr[j] < arr[j - 1]) {
                float t = arr[j]; arr[j] = arr[j - 1]; arr[j - 1] = t;
            }
        }
    }
}

// merge two sorted-descending 5-lists -> top 5 (sorted descending)
__device__ __forceinline__ void merge_desc5(const float* a, const float* b, float* o) {
    int i = 0, j = 0;
#pragma unroll
    for (int k = 0; k < RR; k++) {
        float av = a[i], bv = b[j];
        bool ta = (av >= bv);
        o[k] = ta ? av : bv;
        i += ta; j += !ta;
    }
}
// merge two sorted-ascending 5-lists -> bottom 5 (sorted ascending)
__device__ __forceinline__ void merge_asc5(const float* a, const float* b, float* o) {
    int i = 0, j = 0;
#pragma unroll
    for (int k = 0; k < RR; k++) {
        float av = a[i], bv = b[j];
        bool ta = (av <= bv);
        o[k] = ta ? av : bv;
        i += ta; j += !ta;
    }
}

// ---------------------------------------------------------------------------
// Fused kernel: scores + running top-5/bot-5. grid = (GPB, BB), 256 threads.
// At HBM roofline (88.6% DRAM) — unchanged from R4.
// ---------------------------------------------------------------------------
__global__ __launch_bounds__(256) void chowder_scores_topk_kernel(
    const float* __restrict__ x,
    const float* __restrict__ conv_w,
    const float* __restrict__ conv_b)
{
    __shared__ float4 ws[LL / 4];
    __shared__ float stop[WPB * RR];
    __shared__ float sbot[WPB * RR];

    const int tid  = threadIdx.x;
    const int warp = tid >> 5;
    const int lane = tid & 31;
    const int b    = blockIdx.y;

    for (int i = tid; i < LL / 4; i += blockDim.x)
        ws[i] = reinterpret_cast<const float4*>(conv_w)[i];
    __syncthreads();

    float4 w0  = ws[0 * 32 + lane];
    float4 w1r = ws[1 * 32 + lane];
    float4 w2r = ws[2 * 32 + lane];
    float4 w3r = ws[3 * 32 + lane];

    const int gw = blockIdx.x * WPB + warp;
    const float cb = conv_b[0];
    const float* __restrict__ xb = x + (long long)b * NN * LL;

    float top[RR], bot[RR];
#pragma unroll
    for (int i = 0; i < RR; i++) { top[i] = -CUDART_INF_F; bot[i] = CUDART_INF_F; }

    for (int inst = gw; inst < NN; inst += WARPS_PER_BATCH) {
        const float4* __restrict__ xp =
            reinterpret_cast<const float4*>(xb + (long long)inst * LL);

        float4 v0 = xp[0 * 32 + lane];
        float4 v1 = xp[1 * 32 + lane];
        float4 v2 = xp[2 * 32 + lane];
        float4 v3 = xp[3 * 32 + lane];

        float acc = 0.0f;
        acc = fmaf(v0.x, w0.x,  acc); acc = fmaf(v0.y, w0.y,  acc);
        acc = fmaf(v0.z, w0.z,  acc); acc = fmaf(v0.w, w0.w,  acc);
        acc = fmaf(v1.x, w1r.x, acc); acc = fmaf(v1.y, w1r.y, acc);
        acc = fmaf(v1.z, w1r.z, acc); acc = fmaf(v1.w, w1r.w, acc);
        acc = fmaf(v2.x, w2r.x, acc); acc = fmaf(v2.y, w2r.y, acc);
        acc = fmaf(v2.z, w2r.z, acc); acc = fmaf(v2.w, w2r.w, acc);
        acc = fmaf(v3.x, w3r.x, acc); acc = fmaf(v3.y, w3r.y, acc);
        acc = fmaf(v3.z, w3r.z, acc); acc = fmaf(v3.w, w3r.w, acc);

#pragma unroll
        for (int o = 16; o; o >>= 1)
            acc += __shfl_xor_sync(0xffffffff, acc, o);

        if (lane == 0) {
            float v = acc + cb;
            insert_max(top, v);
            insert_min(bot, v);
        }
    }

    if (lane == 0) {
#pragma unroll
        for (int j = 0; j < RR; j++) {
            stop[warp * RR + j] = top[j];
            sbot[warp * RR + j] = bot[j];
        }
    }
    __syncthreads();

    if (tid == 0) {
        float ft[RR], fb[RR];
#pragma unroll
        for (int i = 0; i < RR; i++) { ft[i] = -CUDART_INF_F; fb[i] = CUDART_INF_F; }
        for (int i = 0; i < WPB * RR; i++) {
            insert_max(ft, stop[i]);
            insert_min(fb, sbot[i]);
        }
        float* pt = g_part_top + ((long long)b * GPB + blockIdx.x) * RR;
        float* pb = g_part_bot + ((long long)b * GPB + blockIdx.x) * RR;
        // ft sorted descending, fb sorted ascending (insertion invariant)
#pragma unroll
        for (int j = 0; j < RR; j++) { pt[j] = ft[j]; pb[j] = fb[j]; }
    }
}

// ---------------------------------------------------------------------------
// Merge kernel v2: parallel staging + log-depth tournament merge + MLP.
// grid = BB, 256 threads.
// ---------------------------------------------------------------------------
__global__ __launch_bounds__(256) void chowder_merge_mlp_kernel(
    const float* __restrict__ w1, const float* __restrict__ b1,
    const float* __restrict__ w2, const float* __restrict__ b2,
    const float* __restrict__ w3, const float* __restrict__ b3,
    float* __restrict__ out)
{
    const int b   = blockIdx.x;
    const int tid = threadIdx.x;

    __shared__ float stop[GPB * RR];   // 1280 floats, sorted-desc 5-groups
    __shared__ float sbot[GPB * RR];   // 1280 floats, sorted-asc 5-groups
    __shared__ float cat[2 * RR];
    __shared__ float h1[200];
    __shared__ float h2p[200];         // h2 partials: [0..99]=k-half0, [100..199]=k-half1
    __shared__ float h2[100];

    // ---- stage partials into shared: coalesced, one latency exposure ----
    {
        const float* pt = g_part_top + (long long)b * GPB * RR;
        const float* pb = g_part_bot + (long long)b * GPB * RR;
#pragma unroll
        for (int i = tid; i < GPB * RR; i += 256) {
            stop[i] = pt[i];
            sbot[i] = pb[i];
        }
    }
    __syncthreads();

    // ---- tournament: 256 sorted 5-lists -> 1, log2(256)=8 levels ----
    for (int cnt = GPB; cnt > 1; cnt >>= 1) {
        int half = cnt >> 1;
        if (tid < half) {
            float a[RR], c[RR], o[RR];
#pragma unroll
            for (int j = 0; j < RR; j++) { a[j] = stop[tid * RR + j]; c[j] = stop[(tid + half) * RR + j]; }
            merge_desc5(a, c, o);
#pragma unroll
            for (int j = 0; j < RR; j++) stop[tid * RR + j] = o[j];

#pragma unroll
            for (int j = 0; j < RR; j++) { a[j] = sbot[tid * RR + j]; c[j] = sbot[(tid + half) * RR + j]; }
            merge_asc5(a, c, o);
#pragma unroll
            for (int j = 0; j < RR; j++) sbot[tid * RR + j] = o[j];
        }
        __syncthreads();
    }

    // cat = [min_vals ascending, max_vals descending]
    if (tid < RR)          cat[tid] = sbot[tid];
    else if (tid < 2 * RR) cat[tid] = stop[tid - RR];
    __syncthreads();

    // ---- tiny MLP (no activations) ----
    // h1[200] = cat[10] @ w1[10,200] + b1  (coalesced column loads)
    if (tid < 200) {
        float a = b1[tid];
#pragma unroll
        for (int i = 0; i < 2 * RR; i++)
            a = fmaf(cat[i], w1[i * 200 + tid], a);
        h1[tid] = a;
    }
    __syncthreads();
    // h2[100] = h1[200] @ w2[200,100] + b2 — k split over 2 groups of 100
    if (tid < 200) {
        const int o    = tid % 100;
        const int k0   = (tid / 100) * 100;
        float a = 0.0f;
#pragma unroll 4
        for (int k = 0; k < 100; k++)
            a = fmaf(h1[k0 + k], w2[(k0 + k) * 100 + o], a);
        h2p[tid] = a;
    }
    __syncthreads();
    if (tid < 100)
        h2[tid] = h2p[tid] + h2p[100 + tid] + b2[tid];
    __syncthreads();
    // out[2] = h2[100] @ w3[100,2] + b3 — k split over 32 lanes per channel
    if (tid < 64) {
        const int c = tid >> 5;         // output channel (warp-contiguous)
        const int g = tid & 31;         // k-lane within channel
        float a = 0.0f;
        for (int k = g; k < 100; k += 32)
            a = fmaf(h2[k], w3[k * 2 + c], a);
#pragma unroll
        for (int o2 = 16; o2; o2 >>= 1)
            a += __shfl_xor_sync(0xffffffff, a, o2);
        if (g == 0)
            out[b * 2 + c] = a + b3[c];
    }
}

// ---------------------------------------------------------------------------
extern "C" void kernel_launch(void* const* d_in, const int* in_sizes, int n_in,
                              void* d_out, int out_size)
{
    const float* x      = (const float*)d_in[0];
    const float* conv_w = (const float*)d_in[1];
    const float* conv_b = (const float*)d_in[2];
    const float* w1     = (const float*)d_in[3];
    const float* b1     = (const float*)d_in[4];
    const float* w2     = (const float*)d_in[5];
    const float* b2     = (const float*)d_in[6];
    const float* w3     = (const float*)d_in[7];
    const float* b3     = (const float*)d_in[8];
    float* out          = (float*)d_out;

    dim3 grid(GPB, BB);
    chowder_scores_topk_kernel<<<grid, 256>>>(x, conv_w, conv_b);
    chowder_merge_mlp_kernel<<<BB, 256>>>(w1, b1, w2, b2, w3, b3, out);
}